// round 17
// baseline (speedup 1.0000x reference)
#include <cuda_runtime.h>
#include <cuda_bf16.h>

#define Nn 50000
#define Ee 1600000
#define Hh 128
#define Ff 64
#define Gg 50
#define Ll 3
#define NGg 256
#define BINS 8192
#define NBLK 196            // ceil(Nn/256)
#define KP 56               // padded gaussian K

#define CUTOFF 10.0f
#define STEP_  (CUTOFF / (Gg - 1))
#define COEFF_ (-0.5f / (STEP_ * STEP_))
#define TABMAX 8.6700f
#define HSTEP  (TABMAX / (BINS - 1))
#define INVH   ((BINS - 1) / TABMAX)
#define LN2    0.69314718055994531f
#define PI_F   3.14159265358979f

// ---------------- scratch ----------------
__device__ __align__(16) float g_h[Nn * Hh];
__device__ __align__(16) unsigned g_xb[Nn * 32];       // bf16x2 t1 for edge_agg
__device__ __align__(16) float g_agg[Nn * Ff];
__device__ __align__(16) unsigned short g_tabh[(size_t)Ll * BINS * Ff];  // bf16 W*C table
__device__ __align__(16) unsigned g_cse[Ee];           // CSR edges: src | bin<<17
__device__ int g_slot[Ee];
__device__ int g_cnt[Nn];                               // zero-init; scan_c re-zeroes
__device__ int g_rowptr[Nn + 1];
__device__ int g_bsum[256];
__device__ int g_dhist[256];                            // degree histogram (init_h zeroes)
__device__ int g_dcur[256];
__device__ int g_order[Nn];                             // degree-sorted node order

__device__ __forceinline__ float sspf(float x) {
    float t = __expf(x);
    float sp = (x > 15.0f) ? x : __logf(1.0f + t);
    return sp - LN2;
}
__device__ __forceinline__ unsigned f2tf32(float x) {
    unsigned u;
    asm("cvt.rna.tf32.f32 %0, %1;" : "=r"(u) : "f"(x));
    return u;
}
__device__ __forceinline__ unsigned pack_bf16x2(float lo, float hi) {
    unsigned r;
    asm("cvt.rn.bf16x2.f32 %0, %1, %2;" : "=r"(r) : "f"(hi), "f"(lo));
    return r;
}
__device__ __forceinline__ float2 unpack_bf16x2(unsigned p) {
    float2 r;
    r.x = __uint_as_float(p << 16);
    r.y = __uint_as_float(p & 0xFFFF0000u);
    return r;
}
__device__ __forceinline__ void mma8(float* c, const unsigned* a, unsigned b0, unsigned b1) {
    asm volatile(
        "mma.sync.aligned.m16n8k8.row.col.f32.tf32.tf32.f32 "
        "{%0,%1,%2,%3}, {%4,%5,%6,%7}, {%8,%9}, {%0,%1,%2,%3};"
        : "+f"(c[0]), "+f"(c[1]), "+f"(c[2]), "+f"(c[3])
        : "r"(a[0]), "r"(a[1]), "r"(a[2]), "r"(a[3]), "r"(b0), "r"(b1));
}

// ---------------- h init + dst histogram + zero dhist (grid*block == Ee) ------
__global__ void init_h(const int* __restrict__ z, const float* __restrict__ emb,
                       const int* __restrict__ ei) {
    int i = blockIdx.x * 256 + threadIdx.x;     // i < Nn*32 == Ee
    int n = i >> 5, c = i & 31;
    ((float4*)g_h)[i] = ((const float4*)emb)[(size_t)__ldg(z + n) * 32 + c];
    g_slot[i] = atomicAdd(&g_cnt[__ldg(ei + Ee + i)], 1);   // g_cnt zeroed by scan_c / load
    if (i < 256) g_dhist[i] = 0;
}

// ---------------- W(d)*C(d) table via mma: 64-bin tiles, 128 threads ----------
__global__ __launch_bounds__(128) void build_tab_mma(
    const float* __restrict__ mw1, const float* __restrict__ mb1,
    const float* __restrict__ mw2, const float* __restrict__ mb2)
{
    extern __shared__ float smb[];
    unsigned* sA = (unsigned*)smb;            // 64 x 68 (gaussians; reused as sX)
    unsigned* sW = sA + 64 * 68;              // 64 x 72 (weights)
    unsigned* sX = sA;
    int li = blockIdx.y;
    int tid = threadIdx.x;
    int w = tid >> 5, lane = tid & 31, g = lane >> 2, tg = lane & 3;
    int bin0 = blockIdx.x * 64;

    for (int j = tid; j < 64 * KP; j += 128) {
        int r = j / KP, k = j - r * KP;
        float v = 0.0f;
        if (k < Gg) {
            float dd = (bin0 + r) * HSTEP - k * STEP_;
            v = __expf(COEFF_ * dd * dd);
        }
        sA[r * 68 + k] = f2tf32(v);
    }
    for (int j = tid; j < KP * 64; j += 128) {
        int k = j >> 6, n = j & 63;
        float v = (k < Gg) ? __ldg(mw1 + li * Gg * Ff + k * Ff + n) : 0.0f;
        sW[k * 72 + n] = f2tf32(v);
    }
    __syncthreads();

    float acc[8][4];
    #pragma unroll
    for (int nt = 0; nt < 8; nt++)
        #pragma unroll
        for (int j = 0; j < 4; j++) acc[nt][j] = 0.0f;
    #pragma unroll
    for (int s = 0; s < 7; s++) {
        unsigned a[4];
        a[0] = sA[(16 * w + g) * 68 + s * 8 + tg];
        a[1] = sA[(16 * w + 8 + g) * 68 + s * 8 + tg];
        a[2] = sA[(16 * w + g) * 68 + s * 8 + tg + 4];
        a[3] = sA[(16 * w + 8 + g) * 68 + s * 8 + tg + 4];
        #pragma unroll
        for (int nt = 0; nt < 8; nt++) {
            unsigned b0 = sW[(s * 8 + tg) * 72 + nt * 8 + g];
            unsigned b1 = sW[(s * 8 + tg + 4) * 72 + nt * 8 + g];
            mma8(acc[nt], a, b0, b1);
        }
    }
    __syncthreads();
    #pragma unroll
    for (int nt = 0; nt < 8; nt++) {
        int col = nt * 8 + 2 * tg;
        float2 bb = *(const float2*)(mb1 + li * Ff + col);
        int r0 = 16 * w + g;
        sX[r0 * 68 + col]       = f2tf32(sspf(acc[nt][0] + bb.x));
        sX[r0 * 68 + col + 1]   = f2tf32(sspf(acc[nt][1] + bb.y));
        sX[(r0 + 8) * 68 + col]     = f2tf32(sspf(acc[nt][2] + bb.x));
        sX[(r0 + 8) * 68 + col + 1] = f2tf32(sspf(acc[nt][3] + bb.y));
    }
    for (int j = tid; j < 64 * 64; j += 128) {
        int k = j >> 6, n = j & 63;
        sW[k * 72 + n] = f2tf32(__ldg(mw2 + li * Ff * Ff + k * Ff + n));
    }
    __syncthreads();

    #pragma unroll
    for (int nt = 0; nt < 8; nt++)
        #pragma unroll
        for (int j = 0; j < 4; j++) acc[nt][j] = 0.0f;
    #pragma unroll
    for (int s = 0; s < 8; s++) {
        unsigned a[4];
        a[0] = sX[(16 * w + g) * 68 + s * 8 + tg];
        a[1] = sX[(16 * w + 8 + g) * 68 + s * 8 + tg];
        a[2] = sX[(16 * w + g) * 68 + s * 8 + tg + 4];
        a[3] = sX[(16 * w + 8 + g) * 68 + s * 8 + tg + 4];
        #pragma unroll
        for (int nt = 0; nt < 8; nt++) {
            unsigned b0 = sW[(s * 8 + tg) * 72 + nt * 8 + g];
            unsigned b1 = sW[(s * 8 + tg + 4) * 72 + nt * 8 + g];
            mma8(acc[nt], a, b0, b1);
        }
    }
    float C0, C1;
    {
        int r = bin0 + 16 * w + g;
        C0 = 0.5f * (__cosf(r * HSTEP * (PI_F / CUTOFF)) + 1.0f);
        C1 = 0.5f * (__cosf((r + 8) * HSTEP * (PI_F / CUTOFF)) + 1.0f);
    }
    #pragma unroll
    for (int nt = 0; nt < 8; nt++) {
        int col = nt * 8 + 2 * tg;
        float2 bb = *(const float2*)(mb2 + li * Ff + col);
        int bin = bin0 + 16 * w + g;
        ((unsigned*)g_tabh)[((size_t)li * BINS + bin) * 32 + (col >> 1)] =
            pack_bf16x2((acc[nt][0] + bb.x) * C0, (acc[nt][1] + bb.y) * C0);
        ((unsigned*)g_tabh)[((size_t)li * BINS + bin + 8) * 32 + (col >> 1)] =
            pack_bf16x2((acc[nt][2] + bb.x) * C1, (acc[nt][3] + bb.y) * C1);
    }
}

// ---------------- CSR scan ----------------
__global__ void scan_a() {
    __shared__ int s[256];
    int i = blockIdx.x * 256 + threadIdx.x;
    int v = (i < Nn) ? g_cnt[i] : 0;
    s[threadIdx.x] = v;
    __syncthreads();
    for (int o = 128; o > 0; o >>= 1) {
        if (threadIdx.x < o) s[threadIdx.x] += s[threadIdx.x + o];
        __syncthreads();
    }
    if (threadIdx.x == 0) g_bsum[blockIdx.x] = s[0];
}
__global__ void scan_c() {
    __shared__ int s[256];
    __shared__ int bs[256];
    int t = threadIdx.x;
    int i = blockIdx.x * 256 + t;
    int v = (i < Nn) ? g_cnt[i] : 0;
    if (i < Nn) g_cnt[i] = 0;          // re-zero for next replay (zero-init on first run)
    s[t] = v;
    bs[t] = (t < blockIdx.x) ? g_bsum[t] : 0;
    __syncthreads();
    for (int o = 1; o < 256; o <<= 1) {
        int x = (t >= o) ? s[t - o] : 0;
        __syncthreads();
        s[t] += x;
        __syncthreads();
    }
    for (int o = 128; o > 0; o >>= 1) {
        if (t < o) bs[t] += bs[t + o];
        __syncthreads();
    }
    int excl = s[t] - v + bs[0];
    if (i < Nn) {
        g_rowptr[i] = excl;
        if (i == Nn - 1) g_rowptr[Nn] = excl + v;
    }
}

// ---------------- edge prep + CSR fill (no atomics, 4-byte record) ----------------
__global__ void edge_prep_fill(const float* __restrict__ pos, const int* __restrict__ ei) {
    int e = blockIdx.x * 256 + threadIdx.x;
    if (e >= Ee) return;
    int s = __ldg(ei + e);
    int t = __ldg(ei + Ee + e);
    float dx = __ldg(pos + s * 3 + 0) - __ldg(pos + t * 3 + 0);
    float dy = __ldg(pos + s * 3 + 1) - __ldg(pos + t * 3 + 1);
    float dz = __ldg(pos + s * 3 + 2) - __ldg(pos + t * 3 + 2);
    float d = sqrtf(dx * dx + dy * dy + dz * dz);
    int b = (int)(d * INVH + 0.5f);
    if (b > BINS - 1) b = BINS - 1;
    int p = __ldg(&g_rowptr[t]) + g_slot[e];
    g_cse[p] = (unsigned)s | ((unsigned)b << 17);
}

// ---------------- degree counting sort ----------------
__global__ void dhist() {
    int i = blockIdx.x * 256 + threadIdx.x;
    if (i >= Nn) return;
    int deg = __ldg(&g_rowptr[i + 1]) - __ldg(&g_rowptr[i]);
    if (deg > 255) deg = 255;
    atomicAdd(&g_dhist[deg], 1);
}
__global__ void dscan() {
    __shared__ int s[256];
    int t = threadIdx.x;
    s[t] = g_dhist[t];
    __syncthreads();
    for (int o = 1; o < 256; o <<= 1) {
        int v = (t >= o) ? s[t - o] : 0;
        __syncthreads();
        s[t] += v;
        __syncthreads();
    }
    g_dcur[t] = (t == 0) ? 0 : s[t - 1];
}
__global__ void dscatter() {
    int i = blockIdx.x * 256 + threadIdx.x;
    if (i >= Nn) return;
    int deg = __ldg(&g_rowptr[i + 1]) - __ldg(&g_rowptr[i]);
    if (deg > 255) deg = 255;
    int pos = atomicAdd(&g_dcur[deg], 1);
    g_order[pos] = i;
}

// ---------------- standalone mode0: g_xb = bf16(g_h @ l1w[0]) ----------------
__global__ __launch_bounds__(256) void gemm0(const float* __restrict__ Wt)
{
    constexpr int K = 128, NC = 64, NT = 8, PB = 72, PA = 36;
    extern __shared__ float sm[];
    unsigned* As = (unsigned*)sm;
    unsigned* Bs = (unsigned*)(sm + 256 * PA);
    int tid = threadIdx.x;
    int w = tid >> 5, lane = tid & 31, g = lane >> 2, tg = lane & 3;
    int rowBase = blockIdx.x * 256;
    float acc[2][NT][4];
    #pragma unroll
    for (int mt = 0; mt < 2; mt++)
        #pragma unroll
        for (int nt = 0; nt < NT; nt++)
            #pragma unroll
            for (int j = 0; j < 4; j++) acc[mt][nt][j] = 0.0f;
    for (int kc = 0; kc < K; kc += 32) {
        #pragma unroll
        for (int it = 0; it < 8; it++) {
            int idx = it * 256 + tid;
            int row = idx >> 3, q = idx & 7;
            int ar = rowBase + row;
            if (ar > Nn - 1) ar = Nn - 1;
            float4 v = *(const float4*)(g_h + (size_t)ar * K + kc + q * 4);
            unsigned* d = As + row * PA + q * 4;
            d[0] = f2tf32(v.x); d[1] = f2tf32(v.y);
            d[2] = f2tf32(v.z); d[3] = f2tf32(v.w);
        }
        #pragma unroll
        for (int it = 0; it < 2; it++) {
            int idx = it * 256 + tid;
            int k = idx >> 4, n4 = idx & 15;
            float4 v = *(const float4*)(Wt + (size_t)(kc + k) * NC + n4 * 4);
            unsigned* d = Bs + k * PB + n4 * 4;
            d[0] = f2tf32(v.x); d[1] = f2tf32(v.y);
            d[2] = f2tf32(v.z); d[3] = f2tf32(v.w);
        }
        __syncthreads();
        #pragma unroll
        for (int s = 0; s < 4; s++) {
            unsigned a[2][4];
            #pragma unroll
            for (int mt = 0; mt < 2; mt++) {
                int r0 = w * 32 + mt * 16 + g;
                a[mt][0] = As[r0 * PA + s * 8 + tg];
                a[mt][1] = As[(r0 + 8) * PA + s * 8 + tg];
                a[mt][2] = As[r0 * PA + s * 8 + tg + 4];
                a[mt][3] = As[(r0 + 8) * PA + s * 8 + tg + 4];
            }
            #pragma unroll
            for (int nt = 0; nt < NT; nt++) {
                unsigned b0 = Bs[(s * 8 + tg) * PB + nt * 8 + g];
                unsigned b1 = Bs[(s * 8 + tg + 4) * PB + nt * 8 + g];
                mma8(acc[0][nt], a[0], b0, b1);
                mma8(acc[1][nt], a[1], b0, b1);
            }
        }
        __syncthreads();
    }
    #pragma unroll
    for (int mt = 0; mt < 2; mt++) {
        int r0 = rowBase + w * 32 + mt * 16 + g;
        #pragma unroll
        for (int nt = 0; nt < NT; nt++) {
            int col = nt * 8 + tg * 2;
            #pragma unroll
            for (int half = 0; half < 2; half++) {
                int r = r0 + half * 8;
                if (r < Nn)
                    g_xb[(size_t)r * 32 + (col >> 1)] =
                        pack_bf16x2(acc[mt][nt][half * 2], acc[mt][nt][half * 2 + 1]);
            }
        }
    }
}

// ---------------- fused per-layer GEMM chain (2 blocks/SM) ----------------
template <int LAST>
__global__ __launch_bounds__(256, 2) void fused_gemm(
    const float* __restrict__ W1, const float* __restrict__ b1,
    const float* __restrict__ W2, const float* __restrict__ b2,
    const float* __restrict__ W3, const float* __restrict__ ob1v,
    const float* __restrict__ ow2, const float* __restrict__ ob2v,
    const int* __restrict__ batch, float* __restrict__ out)
{
    extern __shared__ float sm[];
    unsigned* R0 = (unsigned*)sm;                 // 9216 words
    unsigned* sX = (unsigned*)(sm + 9216);        // 128 x 132 tf32
    int tid = threadIdx.x;
    int w = tid >> 5, lane = tid & 31, g = lane >> 2, tg = lane & 3;
    int rowBase = blockIdx.x * 128;
    float acc[16][4];

    unsigned* As = R0;
    unsigned* Bs = sX;
    #pragma unroll
    for (int it = 0; it < 8; it++) {
        int idx = it * 256 + tid;
        int row = idx >> 4, q = idx & 15;
        int ar = rowBase + row;
        if (ar > Nn - 1) ar = Nn - 1;
        float4 v = *(const float4*)(g_agg + (size_t)ar * 64 + q * 4);
        unsigned* d = As + row * 68 + q * 4;
        d[0] = f2tf32(v.x); d[1] = f2tf32(v.y); d[2] = f2tf32(v.z); d[3] = f2tf32(v.w);
    }
    #pragma unroll
    for (int it = 0; it < 8; it++) {
        int idx = it * 256 + tid;
        int k = idx >> 5, n4 = idx & 31;
        float4 v = *(const float4*)(W1 + (size_t)k * 128 + n4 * 4);
        unsigned* d = Bs + k * 136 + n4 * 4;
        d[0] = f2tf32(v.x); d[1] = f2tf32(v.y); d[2] = f2tf32(v.z); d[3] = f2tf32(v.w);
    }
    __syncthreads();
    #pragma unroll
    for (int nt = 0; nt < 16; nt++)
        #pragma unroll
        for (int j = 0; j < 4; j++) acc[nt][j] = 0.0f;
    #pragma unroll
    for (int s = 0; s < 8; s++) {
        unsigned a[4];
        a[0] = As[(16 * w + g) * 68 + s * 8 + tg];
        a[1] = As[(16 * w + 8 + g) * 68 + s * 8 + tg];
        a[2] = As[(16 * w + g) * 68 + s * 8 + tg + 4];
        a[3] = As[(16 * w + 8 + g) * 68 + s * 8 + tg + 4];
        #pragma unroll
        for (int nt = 0; nt < 16; nt++) {
            unsigned b0 = Bs[(s * 8 + tg) * 136 + nt * 8 + g];
            unsigned bv1 = Bs[(s * 8 + tg + 4) * 136 + nt * 8 + g];
            mma8(acc[nt], a, b0, bv1);
        }
    }
    __syncthreads();
    #pragma unroll
    for (int nt = 0; nt < 16; nt++) {
        int col = nt * 8 + 2 * tg;
        float2 bb = *(const float2*)(b1 + col);
        int r0 = 16 * w + g;
        sX[r0 * 132 + col]       = f2tf32(sspf(acc[nt][0] + bb.x));
        sX[r0 * 132 + col + 1]   = f2tf32(sspf(acc[nt][1] + bb.y));
        sX[(r0 + 8) * 132 + col]     = f2tf32(sspf(acc[nt][2] + bb.x));
        sX[(r0 + 8) * 132 + col + 1] = f2tf32(sspf(acc[nt][3] + bb.y));
    }

    #pragma unroll
    for (int nt = 0; nt < 16; nt++)
        #pragma unroll
        for (int j = 0; j < 4; j++) acc[nt][j] = 0.0f;
    #pragma unroll
    for (int kc = 0; kc < 128; kc += 64) {
        #pragma unroll
        for (int it = 0; it < 8; it++) {
            int idx = it * 256 + tid;
            int k = idx >> 5, n4 = idx & 31;
            float4 v = *(const float4*)(W2 + (size_t)(kc + k) * 128 + n4 * 4);
            unsigned* d = R0 + k * 136 + n4 * 4;
            d[0] = f2tf32(v.x); d[1] = f2tf32(v.y); d[2] = f2tf32(v.z); d[3] = f2tf32(v.w);
        }
        __syncthreads();
        #pragma unroll
        for (int s = 0; s < 8; s++) {
            unsigned a[4];
            a[0] = sX[(16 * w + g) * 132 + kc + s * 8 + tg];
            a[1] = sX[(16 * w + 8 + g) * 132 + kc + s * 8 + tg];
            a[2] = sX[(16 * w + g) * 132 + kc + s * 8 + tg + 4];
            a[3] = sX[(16 * w + 8 + g) * 132 + kc + s * 8 + tg + 4];
            #pragma unroll
            for (int nt = 0; nt < 16; nt++) {
                unsigned b0 = R0[(s * 8 + tg) * 136 + nt * 8 + g];
                unsigned bv1 = R0[(s * 8 + tg + 4) * 136 + nt * 8 + g];
                mma8(acc[nt], a, b0, bv1);
            }
        }
        __syncthreads();
    }
    #pragma unroll
    for (int nt = 0; nt < 16; nt++) {
        int col = nt * 8 + 2 * tg;
        float2 bb = *(const float2*)(b2 + col);
        #pragma unroll
        for (int half = 0; half < 2; half++) {
            int rl = 16 * w + g + 8 * half;
            int r = rowBase + rl;
            if (r < Nn) {
                float* hp = g_h + (size_t)r * 128 + col;
                float2 ho = *(float2*)hp;
                float ox = acc[nt][2 * half] + bb.x + ho.x;
                float oy = acc[nt][2 * half + 1] + bb.y + ho.y;
                *(float2*)hp = make_float2(ox, oy);
                sX[rl * 132 + col] = f2tf32(ox);
                sX[rl * 132 + col + 1] = f2tf32(oy);
            }
        }
    }
    __syncthreads();

    float acc3[8][4];
    #pragma unroll
    for (int nt = 0; nt < 8; nt++)
        #pragma unroll
        for (int j = 0; j < 4; j++) acc3[nt][j] = 0.0f;
    #pragma unroll
    for (int kc = 0; kc < 128; kc += 64) {
        #pragma unroll
        for (int it = 0; it < 4; it++) {
            int idx = it * 256 + tid;
            int k = idx >> 4, n4 = idx & 15;
            float4 v = *(const float4*)(W3 + (size_t)(kc + k) * 64 + n4 * 4);
            unsigned* d = R0 + k * 72 + n4 * 4;
            d[0] = f2tf32(v.x); d[1] = f2tf32(v.y); d[2] = f2tf32(v.z); d[3] = f2tf32(v.w);
        }
        __syncthreads();
        #pragma unroll
        for (int s = 0; s < 8; s++) {
            unsigned a[4];
            a[0] = sX[(16 * w + g) * 132 + kc + s * 8 + tg];
            a[1] = sX[(16 * w + 8 + g) * 132 + kc + s * 8 + tg];
            a[2] = sX[(16 * w + g) * 132 + kc + s * 8 + tg + 4];
            a[3] = sX[(16 * w + 8 + g) * 132 + kc + s * 8 + tg + 4];
            #pragma unroll
            for (int nt = 0; nt < 8; nt++) {
                unsigned b0 = R0[(s * 8 + tg) * 72 + nt * 8 + g];
                unsigned bv1 = R0[(s * 8 + tg + 4) * 72 + nt * 8 + g];
                mma8(acc3[nt], a, b0, bv1);
            }
        }
        __syncthreads();
    }
    if (!LAST) {
        #pragma unroll
        for (int nt = 0; nt < 8; nt++) {
            int col = nt * 8 + 2 * tg;
            #pragma unroll
            for (int half = 0; half < 2; half++) {
                int r = rowBase + 16 * w + g + 8 * half;
                if (r < Nn)
                    g_xb[(size_t)r * 32 + (col >> 1)] =
                        pack_bf16x2(acc3[nt][2 * half], acc3[nt][2 * half + 1]);
            }
        }
    } else {
        float dot0 = 0.f, dot1 = 0.f;
        #pragma unroll
        for (int nt = 0; nt < 8; nt++) {
            int col = nt * 8 + 2 * tg;
            float2 bb = *(const float2*)(ob1v + col);
            float2 wv = *(const float2*)(ow2 + col);
            dot0 += sspf(acc3[nt][0] + bb.x) * wv.x + sspf(acc3[nt][1] + bb.y) * wv.y;
            dot1 += sspf(acc3[nt][2] + bb.x) * wv.x + sspf(acc3[nt][3] + bb.y) * wv.y;
        }
        dot0 += __shfl_xor_sync(0xFFFFFFFF, dot0, 1);
        dot0 += __shfl_xor_sync(0xFFFFFFFF, dot0, 2);
        dot1 += __shfl_xor_sync(0xFFFFFFFF, dot1, 1);
        dot1 += __shfl_xor_sync(0xFFFFFFFF, dot1, 2);
        if (tg == 0) {
            float o2 = __ldg(ob2v);
            int r = rowBase + 16 * w + g;
            if (r < Nn) atomicAdd(&out[__ldg(batch + r)], dot0 + o2);
            r += 8;
            if (r < Nn) atomicAdd(&out[__ldg(batch + r)], dot1 + o2);
        }
    }
}

// ---------------- edge aggregation: degree-sorted nodes, 4 edge-slots x 8 lanes ----
__device__ __forceinline__ void agg_edge(
    float* acc, const unsigned* __restrict__ cse, int kk,
    const uint4* __restrict__ tabL, const uint4* __restrict__ xb, int fq)
{
    unsigned e = __ldg(&cse[kk]);
    int src = e & 0x1FFFF;
    int b = e >> 17;
    uint4 ta = __ldg(tabL + (size_t)b * 8 + fq);
    uint4 xp = __ldg(xb + (size_t)src * 8 + fq);
    float2 A, X;
    A = unpack_bf16x2(ta.x); X = unpack_bf16x2(xp.x);
    acc[0] += A.x * X.x; acc[1] += A.y * X.y;
    A = unpack_bf16x2(ta.y); X = unpack_bf16x2(xp.y);
    acc[2] += A.x * X.x; acc[3] += A.y * X.y;
    A = unpack_bf16x2(ta.z); X = unpack_bf16x2(xp.z);
    acc[4] += A.x * X.x; acc[5] += A.y * X.y;
    A = unpack_bf16x2(ta.w); X = unpack_bf16x2(xp.w);
    acc[6] += A.x * X.x; acc[7] += A.y * X.y;
}

__global__ __launch_bounds__(256) void edge_agg(int layer) {
    int wslot = (blockIdx.x * 256 + threadIdx.x) >> 5;
    if (wslot >= Nn) return;
    int node = __ldg(&g_order[wslot]);
    int lane = threadIdx.x & 31;
    int eslot = lane >> 3;
    int fq = lane & 7;
    int beg = __ldg(&g_rowptr[node]);
    int end = __ldg(&g_rowptr[node + 1]);
    const uint4* __restrict__ tabL = (const uint4*)(g_tabh + (size_t)layer * BINS * Ff);
    const uint4* __restrict__ xb = (const uint4*)g_xb;
    float acc[8];
    #pragma unroll
    for (int j = 0; j < 8; j++) acc[j] = 0.0f;

    int k = beg;
    for (; k + 7 < end; k += 8) {
        agg_edge(acc, g_cse, k + eslot, tabL, xb, fq);
        agg_edge(acc, g_cse, k + 4 + eslot, tabL, xb, fq);
    }
    for (; k < end; k += 4) {
        if (k + eslot < end)
            agg_edge(acc, g_cse, k + eslot, tabL, xb, fq);
    }
    #pragma unroll
    for (int j = 0; j < 8; j++) {
        acc[j] += __shfl_xor_sync(0xFFFFFFFF, acc[j], 8);
        acc[j] += __shfl_xor_sync(0xFFFFFFFF, acc[j], 16);
    }
    if (eslot == 0) {
        float* dst = g_agg + (size_t)node * Ff + fq * 8;
        *(float4*)dst = make_float4(acc[0], acc[1], acc[2], acc[3]);
        *(float4*)(dst + 4) = make_float4(acc[4], acc[5], acc[6], acc[7]);
    }
}

// ---------------- output ----------------
__global__ void zero_out(float* out) {
    if (threadIdx.x < NGg) out[threadIdx.x] = 0.0f;
}

// ---------------- host ----------------
extern "C" void kernel_launch(void* const* d_in, const int* in_sizes, int n_in,
                              void* d_out, int out_size)
{
    const int*   z    = (const int*)  d_in[0];
    const float* pos  = (const float*)d_in[1];
    const int*   batch= (const int*)  d_in[2];
    const int*   ei   = (const int*)  d_in[3];
    const float* emb  = (const float*)d_in[4];
    const float* mw1  = (const float*)d_in[5];
    const float* mb1  = (const float*)d_in[6];
    const float* mw2  = (const float*)d_in[7];
    const float* mb2  = (const float*)d_in[8];
    const float* l1w  = (const float*)d_in[9];
    const float* l2w  = (const float*)d_in[10];
    const float* l2b  = (const float*)d_in[11];
    const float* lw   = (const float*)d_in[12];
    const float* lb   = (const float*)d_in[13];
    const float* ow1  = (const float*)d_in[14];
    const float* ob1  = (const float*)d_in[15];
    const float* ow2  = (const float*)d_in[16];
    const float* ob2  = (const float*)d_in[17];
    float* out = (float*)d_out;

    const int SM0 = 256 * 36 * 4 + 32 * 72 * 4;
    const int FSM = (9216 + 128 * 132) * 4;                    // 104448
    const int BSM = (64 * 68 + 64 * 72) * 4;                   // 35840
    cudaFuncSetAttribute(gemm0, cudaFuncAttributeMaxDynamicSharedMemorySize, SM0);
    cudaFuncSetAttribute(fused_gemm<0>, cudaFuncAttributeMaxDynamicSharedMemorySize, FSM);
    cudaFuncSetAttribute(fused_gemm<1>, cudaFuncAttributeMaxDynamicSharedMemorySize, FSM);
    cudaFuncSetAttribute(build_tab_mma, cudaFuncAttributeMaxDynamicSharedMemorySize, BSM);

    init_h<<<Nn * Hh / 4 / 256, 256>>>(z, emb, ei);                    // 0
    build_tab_mma<<<dim3(BINS / 64, Ll), 128, BSM>>>(mw1, mb1, mw2, mb2);  // 1
    scan_a<<<NBLK, 256>>>();                                           // 2
    scan_c<<<NBLK, 256>>>();                                           // 3
    edge_prep_fill<<<(Ee + 255) / 256, 256>>>(pos, ei);                // 4
    dhist<<<NBLK, 256>>>();                                            // 5
    dscan<<<1, 256>>>();                                               // 6
    dscatter<<<NBLK, 256>>>();                                         // 7
    gemm0<<<NBLK, 256, SM0>>>(l1w);                                    // 8

    const int NBF = (Nn + 127) / 128;                  // 391
    for (int i = 0; i < Ll; i++) {
        edge_agg<<<(Nn * 32 + 255) / 256, 256>>>(i);
        if (i < Ll - 1) {
            fused_gemm<0><<<NBF, 256, FSM>>>(
                l2w + i * Ff * Hh, l2b + i * Hh,
                lw + i * Hh * Hh, lb + i * Hh,
                l1w + (i + 1) * Hh * Ff,
                nullptr, nullptr, nullptr, nullptr, nullptr);
        } else {
            zero_out<<<1, 256>>>(out);
            fused_gemm<1><<<NBF, 256, FSM>>>(
                l2w + i * Ff * Hh, l2b + i * Hh,
                lw + i * Hh * Hh, lb + i * Hh,
                ow1, ob1, ow2, ob2, batch, out);
        }
    }
}